// round 5
// baseline (speedup 1.0000x reference)
#include <cuda_runtime.h>
#include <cuda_bf16.h>
#include <math.h>
#include <stdint.h>

#define B 8
#define N 56
#define HW 3136           // 56*56
#define TOK 25088         // 8*56*56
#define EMBED 192
#define D1 576
#define TWO_N 112
#define RPE_H 32

// ---------------- device scratch ----------------
__device__ float g_p[TOK * D1];
__device__ float g_qv[TOK * D1];
__device__ float g_t[TOK * D1];
__device__ float g_a[2 * TWO_N * D1];   // a1 then a2
__device__ float g_h[2 * TWO_N * RPE_H];

__device__ __forceinline__ float silu_f(float x) { return x / (1.0f + expf(-x)); }

__device__ __forceinline__ uint32_t to_tf32(float x) {
    uint32_t r;
    asm("cvt.rna.tf32.f32 %0, %1;" : "=r"(r) : "f"(x));
    return r;
}

// hi/lo split for 3xTF32 (error ~2^-22, i.e. fp32-equivalent after dropping lo*lo)
__device__ __forceinline__ void split_tf32(float x, uint32_t& hi, uint32_t& lo) {
    uint32_t h = to_tf32(x);
    hi = h;
    lo = to_tf32(x - __uint_as_float(h));
}

__device__ __forceinline__ void mma_tf32(float c[4], const uint32_t a[4], const uint32_t b[2]) {
    asm volatile(
        "mma.sync.aligned.m16n8k8.row.col.f32.tf32.tf32.f32 "
        "{%0,%1,%2,%3}, {%4,%5,%6,%7}, {%8,%9}, {%0,%1,%2,%3};"
        : "+f"(c[0]), "+f"(c[1]), "+f"(c[2]), "+f"(c[3])
        : "r"(a[0]), "r"(a[1]), "r"(a[2]), "r"(a[3]), "r"(b[0]), "r"(b[1]));
}

// ---------------- kernel A1: RPE hidden layers ----------------
__global__ void rpe_hidden_kernel(const float* __restrict__ w0a, const float* __restrict__ b0a,
                                  const float* __restrict__ wsa, const float* __restrict__ bsa,
                                  const float* __restrict__ w0b, const float* __restrict__ b0b,
                                  const float* __restrict__ wsb, const float* __restrict__ bsb) {
    int t = threadIdx.x;
    int tno = t >> 7;       // 0 or 1
    int row = t & 127;
    if (row >= TWO_N) return;
    const float* W0 = tno ? w0b : w0a;
    const float* B0 = tno ? b0b : b0a;
    const float* WS = tno ? wsb : wsa;
    const float* BS = tno ? bsb : bsa;

    float tv;
    if (row == 0 || row == 56) tv = 0.0f;
    else if (row < 56) tv = (float)row;
    else tv = -(float)(row - 56);

    float h[RPE_H];
#pragma unroll
    for (int j = 0; j < RPE_H; j++) h[j] = tv * W0[j] + B0[j];

    for (int L = 0; L < 3; L++) {
        float hn[RPE_H];
#pragma unroll
        for (int j = 0; j < RPE_H; j++) {
            float s = BS[L * RPE_H + j];
#pragma unroll
            for (int k = 0; k < RPE_H; k++)
                s += fmaxf(h[k], 0.0f) * WS[L * RPE_H * RPE_H + j * RPE_H + k];
            hn[j] = s;
        }
#pragma unroll
        for (int j = 0; j < RPE_H; j++) h[j] = hn[j];
    }
#pragma unroll
    for (int k = 0; k < RPE_H; k++)
        g_h[(tno * TWO_N + row) * RPE_H + k] = fmaxf(h[k], 0.0f);
}

// ---------------- kernel A2: RPE output layer * decay ----------------
__global__ void rpe_out_kernel(const float* __restrict__ wo1, const float* __restrict__ bo1,
                               const float* __restrict__ wo2, const float* __restrict__ bo2,
                               const float* __restrict__ slope) {
    int bx = blockIdx.x;            // 0..223
    int tno = bx / TWO_N;
    int row = bx % TWO_N;
    const float* WO = tno ? wo2 : wo1;
    const float* BO = tno ? bo2 : bo1;

    __shared__ float hs[RPE_H];
    if (threadIdx.x < RPE_H)
        hs[threadIdx.x] = g_h[(tno * TWO_N + row) * RPE_H + threadIdx.x];
    __syncthreads();

    int e;
    if (row == 0 || row == 56) e = 0;
    else if (row < 56) e = row;
    else e = TWO_N - row;

    for (int d = threadIdx.x; d < D1; d += blockDim.x) {
        float s = BO[d];
#pragma unroll
        for (int k = 0; k < RPE_H; k++) s += hs[k] * WO[d * RPE_H + k];
        float sl = slope[d];
        sl = fminf(fmaxf(sl, 0.0f), 1.0f);
        sl = 0.95f + 0.05f * sl;
        float dec = (e == 0) ? 1.0f : powf(sl, (float)e);
        g_a[(tno * TWO_N + row) * D1 + d] = s * dec;
    }
}

// ---------------- kernel B: fused p / q*v GEMMs (TF32 mma) ----------------
#define APITCH 136   // ≡ 8 mod 32 -> conflict-free frag loads
#define BPITCH 72    // ≡ 8 mod 32
__global__ __launch_bounds__(256, 1) void pqv_kernel(
    const float* __restrict__ x,
    const float* __restrict__ pw, const float* __restrict__ pb,
    const float* __restrict__ qw, const float* __restrict__ qb,
    const float* __restrict__ vw, const float* __restrict__ vb) {
    __shared__ float As[32][APITCH];          // [k][m], tf32 bits
    __shared__ float Bs[3][32][BPITCH];       // [mat][k][n], tf32 bits

    int tid = threadIdx.x;
    int warp = tid >> 5, lane = tid & 31;
    int wm = (warp >> 1) * 32;
    int wn = (warp & 1) * 32;
    int quad = lane >> 2, tid4 = lane & 3;
    int m0 = blockIdx.y * 128, n0 = blockIdx.x * 64;

    int lrow = tid >> 1;
    int lcb  = (tid & 1) * 16;
    int wrow = tid >> 2;
    int wkb  = (tid & 3) * 8;

    const float* wmats[3] = {pw, qw, vw};

    float c[3][2][4][4];
#pragma unroll
    for (int mt2 = 0; mt2 < 3; mt2++)
#pragma unroll
        for (int i = 0; i < 2; i++)
#pragma unroll
            for (int j = 0; j < 4; j++)
#pragma unroll
                for (int r = 0; r < 4; r++) c[mt2][i][j][r] = 0.0f;

    for (int kb = 0; kb < EMBED; kb += 32) {
#pragma unroll
        for (int v = 0; v < 4; v++) {
            float4 a = *(const float4*)&x[(m0 + lrow) * EMBED + kb + lcb + v * 4];
            As[lcb + v * 4 + 0][lrow] = __uint_as_float(to_tf32(a.x));
            As[lcb + v * 4 + 1][lrow] = __uint_as_float(to_tf32(a.y));
            As[lcb + v * 4 + 2][lrow] = __uint_as_float(to_tf32(a.z));
            As[lcb + v * 4 + 3][lrow] = __uint_as_float(to_tf32(a.w));
        }
#pragma unroll
        for (int mat = 0; mat < 3; mat++) {
            const float* W = wmats[mat];
            float4 w0 = *(const float4*)&W[(n0 + wrow) * EMBED + kb + wkb];
            float4 w1 = *(const float4*)&W[(n0 + wrow) * EMBED + kb + wkb + 4];
            Bs[mat][wkb + 0][wrow] = __uint_as_float(to_tf32(w0.x));
            Bs[mat][wkb + 1][wrow] = __uint_as_float(to_tf32(w0.y));
            Bs[mat][wkb + 2][wrow] = __uint_as_float(to_tf32(w0.z));
            Bs[mat][wkb + 3][wrow] = __uint_as_float(to_tf32(w0.w));
            Bs[mat][wkb + 4][wrow] = __uint_as_float(to_tf32(w1.x));
            Bs[mat][wkb + 5][wrow] = __uint_as_float(to_tf32(w1.y));
            Bs[mat][wkb + 6][wrow] = __uint_as_float(to_tf32(w1.z));
            Bs[mat][wkb + 7][wrow] = __uint_as_float(to_tf32(w1.w));
        }
        __syncthreads();

#pragma unroll
        for (int k8 = 0; k8 < 32; k8 += 8) {
            uint32_t a[2][4];
#pragma unroll
            for (int mt = 0; mt < 2; mt++) {
                int mb = wm + mt * 16;
                a[mt][0] = __float_as_uint(As[k8 + tid4][mb + quad]);
                a[mt][1] = __float_as_uint(As[k8 + tid4][mb + quad + 8]);
                a[mt][2] = __float_as_uint(As[k8 + tid4 + 4][mb + quad]);
                a[mt][3] = __float_as_uint(As[k8 + tid4 + 4][mb + quad + 8]);
            }
#pragma unroll
            for (int mat = 0; mat < 3; mat++) {
#pragma unroll
                for (int nt = 0; nt < 4; nt++) {
                    uint32_t b[2];
                    int nb = wn + nt * 8 + quad;
                    b[0] = __float_as_uint(Bs[mat][k8 + tid4][nb]);
                    b[1] = __float_as_uint(Bs[mat][k8 + tid4 + 4][nb]);
#pragma unroll
                    for (int mt = 0; mt < 2; mt++)
                        mma_tf32(c[mat][mt][nt], a[mt], b);
                }
            }
        }
        __syncthreads();
    }

#pragma unroll
    for (int mt = 0; mt < 2; mt++) {
#pragma unroll
        for (int half = 0; half < 2; half++) {
            int m = m0 + wm + mt * 16 + quad + half * 8;
#pragma unroll
            for (int nt = 0; nt < 4; nt++) {
                int n = n0 + wn + nt * 8 + tid4 * 2;
                float cp0 = c[0][mt][nt][half * 2 + 0] + pb[n];
                float cp1 = c[0][mt][nt][half * 2 + 1] + pb[n + 1];
                float cq0 = c[1][mt][nt][half * 2 + 0] + qb[n];
                float cq1 = c[1][mt][nt][half * 2 + 1] + qb[n + 1];
                float cv0 = c[2][mt][nt][half * 2 + 0] + vb[n];
                float cv1 = c[2][mt][nt][half * 2 + 1] + vb[n + 1];
                float2 pv = make_float2(silu_f(cp0), silu_f(cp1));
                float2 qv = make_float2(silu_f(cq0) * silu_f(cv0),
                                        silu_f(cq1) * silu_f(cv1));
                *(float2*)&g_p[m * D1 + n] = pv;
                *(float2*)&g_qv[m * D1 + n] = qv;
            }
        }
    }
}

// ---------------- kernel C: axial Toeplitz + gate (TF32 tensor-core) ----------------
// Block = (b, 8-channel group), 512 threads = 16 warps.
// Warp w: channel d = w&7, axis = w>>3 (0: o1 = X·A1 along width, 1: o2 = A2·X along height).
// Per-channel 64x64 (padded) smem plane, pitch 72 floats. Coeff vectors a1p/a2p[d][128]
// hold a[(idx-63) mod 112] so A_mat[k][n] = a[(n-k) mod 112] = ap[n-k+63] (range [0,126]).
// 3xTF32 (hi*hi + hi*lo + lo*hi) keeps this stage fp32-accurate.
#define XPL   4608    // plane: 64 rows * 72
#define XPIT  72
#define RPL   1940    // res plane: 32 rows * 60 (+20 pad, shifts q-banks)
#define RPIT  60
#define XOFF  0
#define A1OFF (8 * XPL)            // 36864
#define A2OFF (A1OFF + 8 * 128)    // 37888
#define RESOFF (A2OFF + 8 * 128)   // 38912
#define SMEMC_FLOATS (RESOFF + 8 * RPL)   // 54432 floats = 217728 B

__global__ __launch_bounds__(512, 1) void toeplitz_kernel() {
    extern __shared__ float sm[];

    int dg = blockIdx.x;                    // 0..71
    int b  = blockIdx.y;                    // 0..7
    int dbase = dg * 8;
    int tid = threadIdx.x;

    // ---- zero the X planes (covers padding rows/cols) ----
    for (int idx = tid; idx < (8 * XPL) / 4; idx += 512)
        *(float4*)&sm[XOFF + idx * 4] = make_float4(0.f, 0.f, 0.f, 0.f);
    __syncthreads();

    // ---- load qv slab into per-channel planes ----
    for (int idx = tid; idx < HW * 2; idx += 512) {
        int pos = idx >> 1;
        int q = (idx & 1) * 4;
        float4 v = *(const float4*)&g_qv[(size_t)(b * HW + pos) * D1 + dbase + q];
        int i = pos / N, j = pos % N;
        int base = i * XPIT + j;
        sm[XOFF + (q + 0) * XPL + base] = v.x;
        sm[XOFF + (q + 1) * XPL + base] = v.y;
        sm[XOFF + (q + 2) * XPL + base] = v.z;
        sm[XOFF + (q + 3) * XPL + base] = v.w;
    }
    // ---- coefficient vectors: ap[d][k] = a[(k-63) mod 112][dbase+d] ----
    for (int idx = tid; idx < 8 * 128; idx += 512) {
        int dd = idx >> 7, k = idx & 127;
        int src = (k + 49) % TWO_N;
        sm[A1OFF + idx] = g_a[src * D1 + dbase + dd];
        sm[A2OFF + idx] = g_a[TWO_N * D1 + src * D1 + dbase + dd];
    }
    __syncthreads();

    int w = tid >> 5, lane = tid & 31;
    int d = w & 7, axis = w >> 3;
    int g = lane >> 2, t4 = lane & 3;
    float* X  = sm + XOFF + d * XPL;
    float* A1 = sm + A1OFF + d * 128;
    float* A2 = sm + A2OFF + d * 128;

    for (int h = 0; h < 2; h++) {
        int M0 = h * 32;
        float C[2][7][4];
#pragma unroll
        for (int mt = 0; mt < 2; mt++)
#pragma unroll
            for (int nt = 0; nt < 7; nt++)
#pragma unroll
                for (int r = 0; r < 4; r++) C[mt][nt][r] = 0.0f;

        if (axis == 0) {
            // o1[i][j] = sum_jp X[i][jp] * a1[(j-jp) mod 112]
            for (int kt = 0; kt < 8; kt++) {
                int k0 = kt * 8;
                uint32_t ah[2][4], al[2][4];
#pragma unroll
                for (int mt = 0; mt < 2; mt++) {
                    int r0 = M0 + mt * 16;
                    split_tf32(X[(r0 + g) * XPIT + k0 + t4],         ah[mt][0], al[mt][0]);
                    split_tf32(X[(r0 + g + 8) * XPIT + k0 + t4],     ah[mt][1], al[mt][1]);
                    split_tf32(X[(r0 + g) * XPIT + k0 + t4 + 4],     ah[mt][2], al[mt][2]);
                    split_tf32(X[(r0 + g + 8) * XPIT + k0 + t4 + 4], ah[mt][3], al[mt][3]);
                }
#pragma unroll
                for (int nt = 0; nt < 7; nt++) {
                    int idx0 = nt * 8 + g - k0 - t4 + 63;
                    uint32_t bh[2], bl[2];
                    split_tf32(A1[idx0],     bh[0], bl[0]);
                    split_tf32(A1[idx0 - 4], bh[1], bl[1]);
#pragma unroll
                    for (int mt = 0; mt < 2; mt++) {
                        mma_tf32(C[mt][nt], ah[mt], bh);
                        mma_tf32(C[mt][nt], al[mt], bh);
                        mma_tf32(C[mt][nt], ah[mt], bl);
                    }
                }
            }
        } else {
            // o2[i][j] = sum_ip a2[(i-ip) mod 112] * X[ip][j]
            for (int kt = 0; kt < 8; kt++) {
                int k0 = kt * 8;
                uint32_t ah[2][4], al[2][4];
#pragma unroll
                for (int mt = 0; mt < 2; mt++) {
                    int r0 = M0 + mt * 16;
                    split_tf32(A2[r0 + g - k0 - t4 + 63],         ah[mt][0], al[mt][0]);
                    split_tf32(A2[r0 + g + 8 - k0 - t4 + 63],     ah[mt][1], al[mt][1]);
                    split_tf32(A2[r0 + g - k0 - t4 - 4 + 63],     ah[mt][2], al[mt][2]);
                    split_tf32(A2[r0 + g + 8 - k0 - t4 - 4 + 63], ah[mt][3], al[mt][3]);
                }
#pragma unroll
                for (int nt = 0; nt < 7; nt++) {
                    uint32_t bh[2], bl[2];
                    split_tf32(X[(k0 + t4) * XPIT + nt * 8 + g],     bh[0], bl[0]);
                    split_tf32(X[(k0 + t4 + 4) * XPIT + nt * 8 + g], bh[1], bl[1]);
#pragma unroll
                    for (int mt = 0; mt < 2; mt++) {
                        mma_tf32(C[mt][nt], ah[mt], bh);
                        mma_tf32(C[mt][nt], al[mt], bh);
                        mma_tf32(C[mt][nt], ah[mt], bl);
                    }
                }
            }
        }
        __syncthreads();    // all compute (reads of X) done; res free from prior task

        float* R = sm + RESOFF + d * RPL;
        if (axis == 0) {
#pragma unroll
            for (int mt = 0; mt < 2; mt++) {
                int ia = M0 + mt * 16 + g;
                int ib = ia + 8;
#pragma unroll
                for (int nt = 0; nt < 7; nt++) {
                    int j = nt * 8 + 2 * t4;
                    if (ia < 56) {
                        R[(ia - M0) * RPIT + j]     = C[mt][nt][0];
                        R[(ia - M0) * RPIT + j + 1] = C[mt][nt][1];
                    }
                    if (ib < 56) {
                        R[(ib - M0) * RPIT + j]     = C[mt][nt][2];
                        R[(ib - M0) * RPIT + j + 1] = C[mt][nt][3];
                    }
                }
            }
        }
        __syncthreads();
        if (axis == 1) {
#pragma unroll
            for (int mt = 0; mt < 2; mt++) {
                int ia = M0 + mt * 16 + g;
                int ib = ia + 8;
#pragma unroll
                for (int nt = 0; nt < 7; nt++) {
                    int j = nt * 8 + 2 * t4;
                    if (ia < 56) {
                        R[(ia - M0) * RPIT + j]     += C[mt][nt][0];
                        R[(ia - M0) * RPIT + j + 1] += C[mt][nt][1];
                    }
                    if (ib < 56) {
                        R[(ib - M0) * RPIT + j]     += C[mt][nt][2];
                        R[(ib - M0) * RPIT + j + 1] += C[mt][nt][3];
                    }
                }
            }
        }
        __syncthreads();

        // gated coalesced store: g_t = g_p * (o1 + o2) for rows M0..M0+rows-1
        int rows = (h == 0) ? 32 : 24;
        for (int idx = tid; idx < rows * N * 2; idx += 512) {
            int pos = idx >> 1;           // local (row, j)
            int q = (idx & 1) * 4;
            int ir = pos / N, j = pos % N;
            size_t gidx = (size_t)(b * HW + (M0 + ir) * N + j) * D1 + dbase + q;
            float4 pv = *(const float4*)&g_p[gidx];
            int base = ir * RPIT + j;
            float4 o;
            o.x = pv.x * sm[RESOFF + (q + 0) * RPL + base];
            o.y = pv.y * sm[RESOFF + (q + 1) * RPL + base];
            o.z = pv.z * sm[RESOFF + (q + 2) * RPL + base];
            o.w = pv.w * sm[RESOFF + (q + 3) * RPL + base];
            *(float4*)&g_t[gidx] = o;
        }
        __syncthreads();    // res reused next task (store order safe: next store is after next compute's sync)
    }
}

// ---------------- kernel D: output GEMM (TF32 mma) ----------------
__global__ __launch_bounds__(256, 1) void out_gemm_kernel(
    const float* __restrict__ ow, const float* __restrict__ ob,
    float* __restrict__ out) {
    __shared__ float As[32][APITCH];
    __shared__ float Bs[32][BPITCH];

    int tid = threadIdx.x;
    int warp = tid >> 5, lane = tid & 31;
    int wm = (warp >> 1) * 32;
    int wn = (warp & 1) * 32;
    int quad = lane >> 2, tid4 = lane & 3;
    int m0 = blockIdx.y * 128, n0 = blockIdx.x * 64;

    int lrow = tid >> 1;
    int lcb  = (tid & 1) * 16;
    int wrow = tid >> 2;
    int wkb  = (tid & 3) * 8;

    float c[2][4][4];
#pragma unroll
    for (int i = 0; i < 2; i++)
#pragma unroll
        for (int j = 0; j < 4; j++)
#pragma unroll
            for (int r = 0; r < 4; r++) c[i][j][r] = 0.0f;

    for (int kb = 0; kb < D1; kb += 32) {
#pragma unroll
        for (int v = 0; v < 4; v++) {
            float4 a = *(const float4*)&g_t[(size_t)(m0 + lrow) * D1 + kb + lcb + v * 4];
            As[lcb + v * 4 + 0][lrow] = __uint_as_float(to_tf32(a.x));
            As[lcb + v * 4 + 1][lrow] = __uint_as_float(to_tf32(a.y));
            As[lcb + v * 4 + 2][lrow] = __uint_as_float(to_tf32(a.z));
            As[lcb + v * 4 + 3][lrow] = __uint_as_float(to_tf32(a.w));
        }
        {
            float4 w0 = *(const float4*)&ow[(n0 + wrow) * D1 + kb + wkb];
            float4 w1 = *(const float4*)&ow[(n0 + wrow) * D1 + kb + wkb + 4];
            Bs[wkb + 0][wrow] = __uint_as_float(to_tf32(w0.x));
            Bs[wkb + 1][wrow] = __uint_as_float(to_tf32(w0.y));
            Bs[wkb + 2][wrow] = __uint_as_float(to_tf32(w0.z));
            Bs[wkb + 3][wrow] = __uint_as_float(to_tf32(w0.w));
            Bs[wkb + 4][wrow] = __uint_as_float(to_tf32(w1.x));
            Bs[wkb + 5][wrow] = __uint_as_float(to_tf32(w1.y));
            Bs[wkb + 6][wrow] = __uint_as_float(to_tf32(w1.z));
            Bs[wkb + 7][wrow] = __uint_as_float(to_tf32(w1.w));
        }
        __syncthreads();

#pragma unroll
        for (int k8 = 0; k8 < 32; k8 += 8) {
            uint32_t a[2][4];
#pragma unroll
            for (int mt = 0; mt < 2; mt++) {
                int mb = wm + mt * 16;
                a[mt][0] = __float_as_uint(As[k8 + tid4][mb + quad]);
                a[mt][1] = __float_as_uint(As[k8 + tid4][mb + quad + 8]);
                a[mt][2] = __float_as_uint(As[k8 + tid4 + 4][mb + quad]);
                a[mt][3] = __float_as_uint(As[k8 + tid4 + 4][mb + quad + 8]);
            }
#pragma unroll
            for (int nt = 0; nt < 4; nt++) {
                uint32_t b[2];
                int nb = wn + nt * 8 + quad;
                b[0] = __float_as_uint(Bs[k8 + tid4][nb]);
                b[1] = __float_as_uint(Bs[k8 + tid4 + 4][nb]);
#pragma unroll
                for (int mt = 0; mt < 2; mt++)
                    mma_tf32(c[mt][nt], a[mt], b);
            }
        }
        __syncthreads();
    }

#pragma unroll
    for (int mt = 0; mt < 2; mt++) {
#pragma unroll
        for (int half = 0; half < 2; half++) {
            int m = m0 + wm + mt * 16 + quad + half * 8;
#pragma unroll
            for (int nt = 0; nt < 4; nt++) {
                int n = n0 + wn + nt * 8 + tid4 * 2;
                float2 o = make_float2(c[mt][nt][half * 2 + 0] + ob[n],
                                       c[mt][nt][half * 2 + 1] + ob[n + 1]);
                *(float2*)&out[m * EMBED + n] = o;
            }
        }
    }
}

// ---------------- launch ----------------
extern "C" void kernel_launch(void* const* d_in, const int* in_sizes, int n_in,
                              void* d_out, int out_size) {
    const float* x    = (const float*)d_in[0];
    const float* p_w  = (const float*)d_in[1];
    const float* p_b  = (const float*)d_in[2];
    const float* q_w  = (const float*)d_in[3];
    const float* q_b  = (const float*)d_in[4];
    const float* v_w  = (const float*)d_in[5];
    const float* v_b  = (const float*)d_in[6];
    const float* o_w  = (const float*)d_in[7];
    const float* o_b  = (const float*)d_in[8];
    const float* slope = (const float*)d_in[9];
    const float* t1_w0 = (const float*)d_in[10];
    const float* t1_b0 = (const float*)d_in[11];
    const float* t1_ws = (const float*)d_in[12];
    const float* t1_bs = (const float*)d_in[13];
    const float* t1_wo = (const float*)d_in[14];
    const float* t1_bo = (const float*)d_in[15];
    const float* t2_w0 = (const float*)d_in[16];
    const float* t2_b0 = (const float*)d_in[17];
    const float* t2_ws = (const float*)d_in[18];
    const float* t2_bs = (const float*)d_in[19];
    const float* t2_wo = (const float*)d_in[20];
    const float* t2_bo = (const float*)d_in[21];
    float* out = (float*)d_out;

    static const int smemC = SMEMC_FLOATS * (int)sizeof(float);   // 217728 B
    cudaFuncSetAttribute(toeplitz_kernel, cudaFuncAttributeMaxDynamicSharedMemorySize, smemC);

    rpe_hidden_kernel<<<1, 256>>>(t1_w0, t1_b0, t1_ws, t1_bs, t2_w0, t2_b0, t2_ws, t2_bs);
    rpe_out_kernel<<<2 * TWO_N, 128>>>(t1_wo, t1_bo, t2_wo, t2_bo, slope);
    pqv_kernel<<<dim3(D1 / 64, TOK / 128), 256>>>(x, p_w, p_b, q_w, q_b, v_w, v_b);
    toeplitz_kernel<<<dim3(D1 / 8, B), 512, smemC>>>();
    out_gemm_kernel<<<dim3(EMBED / 64, TOK / 128), 256>>>(o_w, o_b, out);
}